// round 8
// baseline (speedup 1.0000x reference)
#include <cuda_runtime.h>
#include <cuda_fp16.h>
#include <cstdint>

// TransitionLayer: BN(eval)+ReLU+1x1conv(512->256)+avgpool2x2, NCHW fp32.
// pool(conv(act)) == conv(pool(act)) -> GEMM M=50176, K=512, N=256.
// R8: fp16 HMMA 2-term (B split hi/lo prepacked, A single fp16).
//     BK=64 (8 barriers instead of 16), producer in 4 even waves interleaved
//     with the 4 k-step MMA blocks; B frag LDGs grouped 4+4 with prefetch.

#define BN_EPS 1e-5f

constexpr int CIN  = 512;
constexpr int HH   = 56;
constexpr int WW   = 56;
constexpr int COUT = 256;
constexpr int PP   = 28;
constexpr int PIX  = PP * PP;           // 784
constexpr int M_TOTAL = 64 * PIX;       // 50176
constexpr int MT   = 64;
constexpr int BK   = 64;
constexpr int NCH  = CIN / BK;          // 8

// A smem row: 64 fp16 = 128B data + 16B pad = 144B stride.
// ldmatrix banks: (36r + 8ks + 4s) mod 32 -> 4r tiling, conflict-free.
constexpr int ARSB    = 144;
constexpr int A_BYTES = MT * ARSB;            // 9216 per stage
constexpr int TILE_OFF = 4096;
constexpr int SM_TOTAL = TILE_OFF + 2 * A_BYTES;   // 22528

// Prepacked B frags: [kc (32)][nb (32)][lane (32)] -> uint4 {bhi0,bhi1,blo0,blo1}
constexpr int BUNITS = 32 * 32 * 32;    // 32768
__device__ __align__(16) uint4 g_Bfrag[BUNITS];

#define MMA_F16(C, A, B0, B1)                                                \
    asm volatile("mma.sync.aligned.m16n8k16.row.col.f32.f16.f16.f32 "        \
                 "{%0,%1,%2,%3}, {%4,%5,%6,%7}, {%8,%9}, {%0,%1,%2,%3};"     \
                 : "+f"((C)[0]), "+f"((C)[1]), "+f"((C)[2]), "+f"((C)[3])    \
                 : "r"((A)[0]), "r"((A)[1]), "r"((A)[2]), "r"((A)[3]),       \
                   "r"(B0), "r"(B1))

#define LDMX4(R, ADDR)                                                       \
    asm volatile("ldmatrix.sync.aligned.m8n8.x4.shared.b16 {%0,%1,%2,%3}, [%4];" \
                 : "=r"((R)[0]), "=r"((R)[1]), "=r"((R)[2]), "=r"((R)[3])    \
                 : "r"(ADDR))

__device__ __forceinline__ uint32_t smem_u32(const void* p) {
    uint32_t a;
    asm("{ .reg .u64 t; cvta.to.shared.u64 t, %1; cvt.u32.u64 %0, t; }" : "=r"(a) : "l"(p));
    return a;
}
__device__ __forceinline__ void split2_f16(float v0, float v1, uint32_t& hi, uint32_t& lo) {
    __half h0 = __float2half_rn(v0);
    __half h1 = __float2half_rn(v1);
    __half l0 = __float2half_rn(v0 - __half2float(h0));
    __half l1 = __float2half_rn(v1 - __half2float(h1));
    hi = (uint32_t)__half_as_ushort(h0) | ((uint32_t)__half_as_ushort(h1) << 16);
    lo = (uint32_t)__half_as_ushort(l0) | ((uint32_t)__half_as_ushort(l1) << 16);
}
__device__ __forceinline__ uint32_t pack2_f16(float v0, float v1) {
    __half h0 = __float2half_rn(v0);
    __half h1 = __float2half_rn(v1);
    return (uint32_t)__half_as_ushort(h0) | ((uint32_t)__half_as_ushort(h1) << 16);
}
__device__ __forceinline__ void sts64(uint32_t addr, uint32_t a, uint32_t b) {
    asm volatile("st.shared.v2.b32 [%0], {%1,%2};" :: "r"(addr), "r"(a), "r"(b) : "memory");
}

// ---------------- kernel 1: prepack B (hi/lo fp16, fragment-major) ----------------
__global__ void prepack_B(const float* __restrict__ conv_w)
{
    const int idx = blockIdx.x * 256 + threadIdx.x;
    if (idx >= BUNITS) return;
    const int lane = idx & 31;
    const int nb   = (idx >> 5) & 31;
    const int kc   = idx >> 10;            // k16 index 0..31
    const int n  = nb * 8 + (lane >> 2);
    const int k0 = kc * 16 + (lane & 3) * 2;
    const float* wr = conv_w + (size_t)n * CIN;
    uint32_t h0, l0, h1, l1;
    split2_f16(wr[k0],     wr[k0 + 1], h0, l0);
    split2_f16(wr[k0 + 8], wr[k0 + 9], h1, l1);
    g_Bfrag[idx] = make_uint4(h0, h1, l0, l1);
}

// ---------------- kernel 2: main ----------------
__global__ __launch_bounds__(256, 2)
void transition_hmma5_kernel(const float* __restrict__ x,
                             const float* __restrict__ bn_w,
                             const float* __restrict__ bn_b,
                             const float* __restrict__ bn_m,
                             const float* __restrict__ bn_v,
                             float* __restrict__ out)
{
    extern __shared__ __align__(16) uint32_t sm[];
    float* s_scale = reinterpret_cast<float*>(sm);
    float* s_shift = reinterpret_cast<float*>(sm) + 512;
    const uint32_t sbase = smem_u32(sm);

    const int tid  = threadIdx.x;
    const int wid  = tid >> 5;
    const int lane = tid & 31;
    const int wm   = wid & 1;
    const int wn   = wid >> 1;

    for (int c = tid; c < CIN; c += 256) {
        float inv = rsqrtf(bn_v[c] + BN_EPS);
        float sc  = bn_w[c] * inv;
        s_scale[c] = sc;
        s_shift[c] = bn_b[c] - bn_m[c] * sc;
    }

    const int m0 = blockIdx.x * MT;

    // producer: pxl row 0..63, aq channel quarter: channels aq*16 + wave*4 + e
    const int pxl = tid >> 2;
    const int aq  = tid & 3;
    const int mg  = m0 + pxl;
    const int img = mg / PIX;
    const int pr  = mg % PIX;
    const float* xb = x + (size_t)img * (CIN * HH * WW)
                        + (size_t)(2 * (pr / PP)) * WW + 2 * (pr % PP);

    float acc[2][8][4];
    #pragma unroll
    for (int mh = 0; mh < 2; mh++)
        #pragma unroll
        for (int nn = 0; nn < 8; nn++)
            #pragma unroll
            for (int e = 0; e < 4; e++) acc[mh][nn][e] = 0.0f;

    __syncthreads();

    const uint32_t tile0 = sbase + TILE_OFF;
    const uint32_t a_ldm = (uint32_t)((wm * 32 + (lane & 15)) * ARSB + ((lane >> 4) << 4));
    const uint32_t a_st  = (uint32_t)(pxl * ARSB + aq * 32);
    const uint4* bbase = g_Bfrag + (size_t)(wn * 8) * 32 + lane;

    float2 q0[4], q1[4];   // one 4-channel wave of raw x

    auto ldg_wave = [&](int i, int w) {
        const int c0 = i * BK + aq * 16 + w * 4;
        #pragma unroll
        for (int e = 0; e < 4; e++) {
            const float* xp = xb + (size_t)(c0 + e) * (HH * WW);
            q0[e] = *reinterpret_cast<const float2*>(xp);
            q1[e] = *reinterpret_cast<const float2*>(xp + WW);
        }
    };
    auto cvt_sts_wave = [&](int i, int w) {
        const int c0 = i * BK + aq * 16 + w * 4;
        float v[4];
        #pragma unroll
        for (int e = 0; e < 4; e++) {
            const float sc = s_scale[c0 + e], sh = s_shift[c0 + e];
            v[e] = 0.25f * (fmaxf(fmaf(q0[e].x, sc, sh), 0.0f)
                          + fmaxf(fmaf(q0[e].y, sc, sh), 0.0f)
                          + fmaxf(fmaf(q1[e].x, sc, sh), 0.0f)
                          + fmaxf(fmaf(q1[e].y, sc, sh), 0.0f));
        }
        const uint32_t st = tile0 + (uint32_t)((i & 1) * A_BYTES) + a_st + (uint32_t)(w * 8);
        sts64(st, pack2_f16(v[0], v[1]), pack2_f16(v[2], v[3]));
    };

    auto compute_ks = [&](int i, int ks) {
        const uint32_t aa = tile0 + (uint32_t)((i & 1) * A_BYTES) + a_ldm + (uint32_t)(ks * 32);
        uint32_t ah[2][4];
        LDMX4(ah[0], aa);
        LDMX4(ah[1], aa + 16 * ARSB);
        const uint4* bp = bbase + (size_t)(i * 4 + ks) * (32 * 32);
        // group 0 prefetch
        uint4 b[4];
        #pragma unroll
        for (int g0 = 0; g0 < 4; g0++) b[g0] = __ldg(bp + g0 * 32);
        #pragma unroll
        for (int grp = 0; grp < 2; grp++) {
            uint4 bn_[4];
            if (grp == 0) {
                #pragma unroll
                for (int g1 = 0; g1 < 4; g1++) bn_[g1] = __ldg(bp + (4 + g1) * 32);
            }
            #pragma unroll
            for (int j = 0; j < 4; j++) {
                const int nn = grp * 4 + j;
                #pragma unroll
                for (int mh = 0; mh < 2; mh++) {
                    MMA_F16(acc[mh][nn], ah[mh], b[j].x, b[j].y);   // A * Bhi
                    MMA_F16(acc[mh][nn], ah[mh], b[j].z, b[j].w);   // A * Blo
                }
            }
            #pragma unroll
            for (int j = 0; j < 4; j++) b[j] = bn_[j];
        }
    };

    // prologue: fill chunk 0
    #pragma unroll
    for (int w = 0; w < 4; w++) { ldg_wave(0, w); cvt_sts_wave(0, w); }
    __syncthreads();

    #pragma unroll 1
    for (int i = 0; i < NCH; i++) {
        const bool more = (i + 1 < NCH);
        #pragma unroll
        for (int ks = 0; ks < 4; ks++) {
            if (more) ldg_wave(i + 1, ks);
            compute_ks(i, ks);
            if (more) cvt_sts_wave(i + 1, ks);
        }
        __syncthreads();
    }

    // epilogue
    const int fr = lane >> 2;
    const int q2 = (lane & 3) * 2;
    #pragma unroll
    for (int mh = 0; mh < 2; mh++) {
        #pragma unroll
        for (int half = 0; half < 2; half++) {
            const int m  = m0 + wm * 32 + mh * 16 + fr + half * 8;
            const int im = m / PIX;
            const int px = m % PIX;
            float* ob = out + (size_t)im * (COUT * PIX) + px;
            #pragma unroll
            for (int nn = 0; nn < 8; nn++) {
                const int n = wn * 64 + nn * 8 + q2;
                ob[(size_t)n * PIX]       = acc[mh][nn][half * 2];
                ob[(size_t)(n + 1) * PIX] = acc[mh][nn][half * 2 + 1];
            }
        }
    }
}

extern "C" void kernel_launch(void* const* d_in, const int* in_sizes, int n_in,
                              void* d_out, int out_size)
{
    const float* x      = (const float*)d_in[0];
    const float* bn_w   = (const float*)d_in[1];
    const float* bn_b   = (const float*)d_in[2];
    const float* bn_m   = (const float*)d_in[3];
    const float* bn_v   = (const float*)d_in[4];
    const float* conv_w = (const float*)d_in[5];
    float* out = (float*)d_out;

    prepack_B<<<(BUNITS + 255) / 256, 256>>>(conv_w);

    cudaFuncSetAttribute(transition_hmma5_kernel,
                         cudaFuncAttributeMaxDynamicSharedMemorySize, SM_TOTAL);
    transition_hmma5_kernel<<<M_TOTAL / MT, 256, SM_TOTAL>>>(
        x, bn_w, bn_b, bn_m, bn_v, out);
}